// round 13
// baseline (speedup 1.0000x reference)
#include <cuda_runtime.h>

#define NUM_LEVELS 256

__device__ __forceinline__ float quantize_one(float v) {
    // Nearest center of linspace(-1, 1, 256): i = round((v+1)*127.5), clamp [0,255].
    // Round-to-nearest-even via magic-number add/sub (4-cyc FMA pipe, no cvt pipe).
    float t = fmaf(v, 127.5f, 127.5f);
    t = fmaxf(0.0f, fminf(255.0f, t));
    const float MAGIC = 12582912.0f;            // 1.5 * 2^23
    float r = (t + MAGIC) - MAGIC;              // rint(t) for 0 <= t <= 255
    return fmaf(r, 2.0f / 255.0f, -1.0f);       // center = -1 + i * (2/255)
}

// 256-bit global load/store (sm_100+: LDG.E.256 / STG.E.256).
__device__ __forceinline__ void ldg_v8(const float* __restrict__ p, float r[8]) {
    asm volatile("ld.global.v8.f32 {%0,%1,%2,%3,%4,%5,%6,%7}, [%8];"
                 : "=f"(r[0]), "=f"(r[1]), "=f"(r[2]), "=f"(r[3]),
                   "=f"(r[4]), "=f"(r[5]), "=f"(r[6]), "=f"(r[7])
                 : "l"(p));
}
__device__ __forceinline__ void stg_v8(float* __restrict__ p, const float r[8]) {
    asm volatile("st.global.v8.f32 [%0], {%1,%2,%3,%4,%5,%6,%7,%8};"
                 :: "l"(p),
                    "f"(r[0]), "f"(r[1]), "f"(r[2]), "f"(r[3]),
                    "f"(r[4]), "f"(r[5]), "f"(r[6]), "f"(r[7])
                 : "memory");
}

#define VPT 4   // v8 chunks per thread, front-batched (MLP=4 of LDG.256)

__global__ void __launch_bounds__(256) nq_kernel_v8x4(
    const float* __restrict__ x,
    float* __restrict__ out,
    int n8)   // number of float8 chunks
{
    // Block-contiguous layout: block b owns chunks [b*1024, b*1024+1024),
    // thread t handles chunks base + {0,256,512,768} (coalesced per u-slice).
    int base = blockIdx.x * (blockDim.x * VPT) + threadIdx.x;
    const int s = blockDim.x;

    if (base + (VPT - 1) * s < n8) {
        float r0[8], r1[8], r2[8], r3[8];
        // Front-batch all four independent 256-bit loads.
        ldg_v8(x + (size_t)(base + 0 * s) * 8, r0);
        ldg_v8(x + (size_t)(base + 1 * s) * 8, r1);
        ldg_v8(x + (size_t)(base + 2 * s) * 8, r2);
        ldg_v8(x + (size_t)(base + 3 * s) * 8, r3);
        #pragma unroll
        for (int k = 0; k < 8; k++) r0[k] = quantize_one(r0[k]);
        stg_v8(out + (size_t)(base + 0 * s) * 8, r0);
        #pragma unroll
        for (int k = 0; k < 8; k++) r1[k] = quantize_one(r1[k]);
        stg_v8(out + (size_t)(base + 1 * s) * 8, r1);
        #pragma unroll
        for (int k = 0; k < 8; k++) r2[k] = quantize_one(r2[k]);
        stg_v8(out + (size_t)(base + 2 * s) * 8, r2);
        #pragma unroll
        for (int k = 0; k < 8; k++) r3[k] = quantize_one(r3[k]);
        stg_v8(out + (size_t)(base + 3 * s) * 8, r3);
    } else {
        #pragma unroll
        for (int u = 0; u < VPT; u++) {
            int idx = base + u * s;
            if (idx < n8) {
                float r[8];
                ldg_v8(x + (size_t)idx * 8, r);
                #pragma unroll
                for (int k = 0; k < 8; k++) r[k] = quantize_one(r[k]);
                stg_v8(out + (size_t)idx * 8, r);
            }
        }
    }
}

__global__ void __launch_bounds__(256) nq_tail_kernel(
    const float* __restrict__ x,
    float* __restrict__ out,
    int start, int n)
{
    int i = start + blockIdx.x * blockDim.x + threadIdx.x;
    if (i < n) out[i] = quantize_one(x[i]);
}

extern "C" void kernel_launch(void* const* d_in, const int* in_sizes, int n_in,
                              void* d_out, int out_size) {
    const float* x = (const float*)d_in[0];
    float* out = (float*)d_out;
    int n = in_sizes[0];

    int n8 = n / 8;
    if (n8 > 0) {
        const int threads = 256;
        int per_block = threads * VPT;
        int blocks = (n8 + per_block - 1) / per_block;   // 256 blocks for n = 2^21
        nq_kernel_v8x4<<<blocks, threads>>>(x, out, n8);
    }
    int tail_start = n8 * 8;
    int tail = n - tail_start;
    if (tail > 0) {
        nq_tail_kernel<<<1, 256>>>(x, out, tail_start, n);
    }
}